// round 1
// baseline (speedup 1.0000x reference)
#include <cuda_runtime.h>

// ---------------------------------------------------------------------------
// Attention_50921132261730 — full fp32 baseline
//   B=2, C=512, N=2048, H=16, D=64, SCALE=8
//   qkv = Wqkv @ x            (NN gemm, batched over B)
//   q,k <- l2norm over D * scale_vec (SCALE folded into q)
//   S   = q^T k               (TN gemm, batched over B*H)  -> 537MB scratch
//   P   = softmax rows
//   AO  = v @ P^T             (NT gemm, M=64)  (== (P @ v^T)^T, channel-major)
//   out = Wout @ AO + bout    (NN gemm, batched over B)
// ---------------------------------------------------------------------------

constexpr int Bb = 2, Cc = 512, Nn = 2048, HEADS = 16, DHEAD = 64;
constexpr int HDIM = HEADS * DHEAD;            // 1024
constexpr long QKV_ELEMS = (long)Bb * 3 * HDIM * Nn;   // 12,582,912
constexpr long S_ELEMS   = (long)Bb * HEADS * Nn * Nn; // 134,217,728
constexpr long AO_ELEMS  = (long)Bb * HDIM * Nn;       // 4,194,304

__device__ float g_qkv[QKV_ELEMS];
__device__ float g_S[S_ELEMS];
__device__ float g_ao[AO_ELEMS];

// ---------------------------------------------------------------------------
// Generic tiled SGEMM.
// Layouts:
//   TA=false: A[m*lda + k]   (row-major [M,K])
//   TA=true : A[k*lda + m]   ([K,M], m contiguous)
//   TB=false: B[k*ldb + n]   ([K,N], n contiguous)
//   TB=true : B[n*ldb + k]   ([N,K], k contiguous)
//   C[m*ldc + n], optional bias[m].
// Batch: z -> zo=z/innerCnt, zi=z%innerCnt; ptr += zo*s?o + zi*s?i
// ---------------------------------------------------------------------------
template<int BM,int BN,int BK,int TM,int TN,bool TA,bool TB,bool BIAS>
__global__ void __launch_bounds__((BM/TM)*(BN/TN))
gemm_k(const float* __restrict__ Ag, const float* __restrict__ Bg,
       float* __restrict__ Cg, const float* __restrict__ bias,
       int K, int lda, int ldb, int ldc,
       long sAo, long sAi, long sBo, long sBi, long sCo, long sCi,
       int innerCnt)
{
    constexpr int NT = (BM/TM) * (BN/TN);
    __shared__ float As[BK][BM];
    __shared__ float Bs[BK][BN];

    const int z  = blockIdx.z;
    const int zo = z / innerCnt, zi = z - zo * innerCnt;
    const float* A = Ag + (long)zo * sAo + (long)zi * sAi;
    const float* B = Bg + (long)zo * sBo + (long)zi * sBi;
    float*       C = Cg + (long)zo * sCo + (long)zi * sCi;

    const int tid  = threadIdx.x;
    const int m0   = blockIdx.y * BM;
    const int n0   = blockIdx.x * BN;
    const int tcol = tid % (BN/TN);
    const int trow = tid / (BN/TN);

    float acc[TM][TN];
    #pragma unroll
    for (int i = 0; i < TM; i++)
        #pragma unroll
        for (int j = 0; j < TN; j++) acc[i][j] = 0.f;

    for (int k0 = 0; k0 < K; k0 += BK) {
        // ---- load A tile into As[k][m] ----
        if constexpr (TA) {
            constexpr int L = BK*BM/4/NT;
            static_assert(BK*BM/4 >= NT && (BK*BM/4) % NT == 0, "A ldr");
            #pragma unroll
            for (int l = 0; l < L; l++) {
                int idx = tid + l*NT;
                int kk = idx / (BM/4), mq = idx % (BM/4);
                *(float4*)&As[kk][mq*4] =
                    *(const float4*)(A + (long)(k0+kk)*lda + (m0 + mq*4));
            }
        } else {
            constexpr int L = BM*BK/4/NT;
            static_assert(BM*BK/4 >= NT && (BM*BK/4) % NT == 0, "A ldr");
            #pragma unroll
            for (int l = 0; l < L; l++) {
                int idx = tid + l*NT;
                int mm = idx / (BK/4), kq = idx % (BK/4);
                float4 v = *(const float4*)(A + (long)(m0+mm)*lda + (k0 + kq*4));
                As[kq*4+0][mm] = v.x; As[kq*4+1][mm] = v.y;
                As[kq*4+2][mm] = v.z; As[kq*4+3][mm] = v.w;
            }
        }
        // ---- load B tile into Bs[k][n] ----
        if constexpr (!TB) {
            constexpr int L = BK*BN/4/NT;
            static_assert(BK*BN/4 >= NT && (BK*BN/4) % NT == 0, "B ldr");
            #pragma unroll
            for (int l = 0; l < L; l++) {
                int idx = tid + l*NT;
                int kk = idx / (BN/4), nq = idx % (BN/4);
                *(float4*)&Bs[kk][nq*4] =
                    *(const float4*)(B + (long)(k0+kk)*ldb + (n0 + nq*4));
            }
        } else {
            constexpr int L = BN*BK/4/NT;
            static_assert(BN*BK/4 >= NT && (BN*BK/4) % NT == 0, "B ldr");
            #pragma unroll
            for (int l = 0; l < L; l++) {
                int idx = tid + l*NT;
                int nn = idx / (BK/4), kq = idx % (BK/4);
                float4 v = *(const float4*)(B + (long)(n0+nn)*ldb + (k0 + kq*4));
                Bs[kq*4+0][nn] = v.x; Bs[kq*4+1][nn] = v.y;
                Bs[kq*4+2][nn] = v.z; Bs[kq*4+3][nn] = v.w;
            }
        }
        __syncthreads();

        #pragma unroll
        for (int kk = 0; kk < BK; kk++) {
            float a[TM], b[TN];
            #pragma unroll
            for (int i = 0; i < TM; i += 4)
                *(float4*)&a[i] = *(float4*)&As[kk][trow*TM + i];
            #pragma unroll
            for (int j = 0; j < TN; j += 4)
                *(float4*)&b[j] = *(float4*)&Bs[kk][tcol*TN + j];
            #pragma unroll
            for (int i = 0; i < TM; i++)
                #pragma unroll
                for (int j = 0; j < TN; j++)
                    acc[i][j] += a[i] * b[j];
        }
        __syncthreads();
    }

    #pragma unroll
    for (int i = 0; i < TM; i++) {
        int m = m0 + trow*TM + i;
        float bval = BIAS ? bias[m] : 0.f;
        #pragma unroll
        for (int j = 0; j < TN; j += 4) {
            float4 v;
            v.x = acc[i][j+0] + bval;
            v.y = acc[i][j+1] + bval;
            v.z = acc[i][j+2] + bval;
            v.w = acc[i][j+3] + bval;
            *(float4*)(C + (long)m*ldc + (n0 + tcol*TN + j)) = v;
        }
    }
}

// ---------------------------------------------------------------------------
// Fused l2-normalize over head-dim + per-dim scales, in place on q,k regions.
// Folds SCALE=8 into q. One thread per (b, sel, h, n).
// ---------------------------------------------------------------------------
__global__ void norm_scale_k(float* __restrict__ qkv,
                             const float* __restrict__ q_scale,
                             const float* __restrict__ k_scale)
{
    int gid = blockIdx.x * blockDim.x + threadIdx.x; // 131072 total
    int n   = gid & (Nn - 1);
    int h   = (gid >> 11) & (HEADS - 1);
    int sel = (gid >> 15) & 1;   // 0=q, 1=k
    int b   = gid >> 16;

    float* p = qkv + ((long)b * 3 * HDIM + sel * HDIM + h * DHEAD) * Nn + n;
    float v[DHEAD];
    float ss = 0.f;
    #pragma unroll
    for (int d = 0; d < DHEAD; d++) {
        v[d] = p[(long)d * Nn];
        ss += v[d] * v[d];
    }
    float nrm = fmaxf(sqrtf(ss), 1e-12f);
    float inv = (sel ? 1.0f : 8.0f) / nrm;   // fold SCALE into q
    const float* sc = sel ? k_scale : q_scale;
    #pragma unroll
    for (int d = 0; d < DHEAD; d++)
        p[(long)d * Nn] = v[d] * inv * sc[d];
}

// ---------------------------------------------------------------------------
// Row softmax over S: one 256-thread CTA per row of 2048.
// ---------------------------------------------------------------------------
__global__ void softmax_k(float* __restrict__ S)
{
    __shared__ float red[8];
    float* p = S + (long)blockIdx.x * Nn;
    const int t = threadIdx.x;

    float4 v0 = ((const float4*)p)[t];
    float4 v1 = ((const float4*)p)[t + 256];

    float m = fmaxf(fmaxf(fmaxf(v0.x, v0.y), fmaxf(v0.z, v0.w)),
                    fmaxf(fmaxf(v1.x, v1.y), fmaxf(v1.z, v1.w)));
    #pragma unroll
    for (int o = 16; o > 0; o >>= 1) m = fmaxf(m, __shfl_xor_sync(0xffffffffu, m, o));
    if ((t & 31) == 0) red[t >> 5] = m;
    __syncthreads();
    m = red[0];
    #pragma unroll
    for (int w = 1; w < 8; w++) m = fmaxf(m, red[w]);
    __syncthreads();

    v0.x = __expf(v0.x - m); v0.y = __expf(v0.y - m);
    v0.z = __expf(v0.z - m); v0.w = __expf(v0.w - m);
    v1.x = __expf(v1.x - m); v1.y = __expf(v1.y - m);
    v1.z = __expf(v1.z - m); v1.w = __expf(v1.w - m);

    float s = v0.x + v0.y + v0.z + v0.w + v1.x + v1.y + v1.z + v1.w;
    #pragma unroll
    for (int o = 16; o > 0; o >>= 1) s += __shfl_xor_sync(0xffffffffu, s, o);
    if ((t & 31) == 0) red[t >> 5] = s;
    __syncthreads();
    s = red[0];
    #pragma unroll
    for (int w = 1; w < 8; w++) s += red[w];

    float inv = 1.0f / s;
    v0.x *= inv; v0.y *= inv; v0.z *= inv; v0.w *= inv;
    v1.x *= inv; v1.y *= inv; v1.z *= inv; v1.w *= inv;
    ((float4*)p)[t]       = v0;
    ((float4*)p)[t + 256] = v1;
}

// ---------------------------------------------------------------------------
extern "C" void kernel_launch(void* const* d_in, const int* in_sizes, int n_in,
                              void* d_out, int out_size)
{
    (void)in_sizes; (void)n_in; (void)out_size;
    const float* x       = (const float*)d_in[0]; // [2,512,2048]
    const float* Wqkv    = (const float*)d_in[1]; // [3072,512]
    const float* q_scale = (const float*)d_in[2]; // [64]
    const float* k_scale = (const float*)d_in[3]; // [64]
    const float* Wout    = (const float*)d_in[4]; // [512,1024]
    const float* bout    = (const float*)d_in[5]; // [512]
    float* out = (float*)d_out;                   // [2,512,2048]

    float *qkv, *S, *ao;
    cudaGetSymbolAddress((void**)&qkv, g_qkv);
    cudaGetSymbolAddress((void**)&S,   g_S);
    cudaGetSymbolAddress((void**)&ao,  g_ao);

    // 1) qkv = Wqkv @ x        M=3072 N=2048 K=512, batch B=2
    gemm_k<128,128,8,8,8,false,false,false>
        <<<dim3(Nn/128, 3072/128, Bb), 256>>>(
            Wqkv, x, qkv, nullptr,
            Cc, /*lda*/Cc, /*ldb*/Nn, /*ldc*/Nn,
            0, 0, (long)Cc*Nn, 0, (long)3*HDIM*Nn, 0, 1);

    // 2) l2-normalize q,k (+scales, SCALE folded into q), in place
    norm_scale_k<<<(Bb*2*HEADS*Nn)/256, 256>>>(qkv, q_scale, k_scale);

    // 3) S = q^T k    per (b,h): M=N=2048, K=64
    gemm_k<128,128,8,8,8,true,false,false>
        <<<dim3(Nn/128, Nn/128, Bb*HEADS), 256>>>(
            qkv /*q*/, qkv + (long)HDIM*Nn /*k*/, S, nullptr,
            DHEAD, /*lda*/Nn, /*ldb*/Nn, /*ldc*/Nn,
            (long)3*HDIM*Nn, (long)DHEAD*Nn,
            (long)3*HDIM*Nn, (long)DHEAD*Nn,
            (long)HEADS*Nn*Nn, (long)Nn*Nn, HEADS);

    // 4) row softmax of S
    softmax_k<<<Bb*HEADS*Nn, 256>>>(S);

    // 5) AO[d,i] = sum_j v[d,j] * P[i,j]   per (b,h): M=64, N=2048, K=2048
    gemm_k<64,128,8,8,8,false,true,false>
        <<<dim3(Nn/128, 1, Bb*HEADS), 128>>>(
            qkv + (long)2*HDIM*Nn /*v*/, S, ao, nullptr,
            Nn, /*lda*/Nn, /*ldb*/Nn, /*ldc*/Nn,
            (long)3*HDIM*Nn, (long)DHEAD*Nn,
            (long)HEADS*Nn*Nn, (long)Nn*Nn,
            (long)HDIM*Nn, (long)DHEAD*Nn, HEADS);

    // 6) out = Wout @ AO + bout   M=512 N=2048 K=1024, batch B=2
    gemm_k<128,128,8,8,8,false,false,true>
        <<<dim3(Nn/128, Cc/128, Bb), 256>>>(
            Wout, ao, out, bout,
            HDIM, /*lda*/HDIM, /*ldb*/Nn, /*ldc*/Nn,
            0, 0, (long)HDIM*Nn, 0, (long)Cc*Nn, 0, 1);
}

// round 2
// speedup vs baseline: 1.3081x; 1.3081x over previous
#include <cuda_runtime.h>
#include <mma.h>

using namespace nvcuda;

// ---------------------------------------------------------------------------
// Attention_50921132261730 — R2: fused tf32-WMMA flash attention
//   B=2, C=512, N=2048, H=16, D=64, SCALE=8
//   qkv = Wqkv @ x            (fp32 NN gemm, batched over B)
//   q,k <- l2norm over D * scale_vec (SCALE folded into q)
//   flash: S=q^T k, P=exp(S) (no max-shift; |S|<=8), O=P@V^T, O/=rowsum
//   out = Wout @ AO + bout    (fp32 NN gemm, batched over B)
// ---------------------------------------------------------------------------

constexpr int Bb = 2, Cc = 512, Nn = 2048, HEADS = 16, DHEAD = 64;
constexpr int HDIM = HEADS * DHEAD;            // 1024
constexpr long QKV_ELEMS = (long)Bb * 3 * HDIM * Nn;   // 12,582,912
constexpr long AO_ELEMS  = (long)Bb * HDIM * Nn;       // 4,194,304

__device__ float g_qkv[QKV_ELEMS];
__device__ float g_ao[AO_ELEMS];

// ---------------------------------------------------------------------------
// Generic tiled fp32 SGEMM (unchanged from R1; used for qkv and out)
// ---------------------------------------------------------------------------
template<int BM,int BN,int BK,int TM,int TN,bool TA,bool TB,bool BIAS>
__global__ void __launch_bounds__((BM/TM)*(BN/TN))
gemm_k(const float* __restrict__ Ag, const float* __restrict__ Bg,
       float* __restrict__ Cg, const float* __restrict__ bias,
       int K, int lda, int ldb, int ldc,
       long sAo, long sAi, long sBo, long sBi, long sCo, long sCi,
       int innerCnt)
{
    constexpr int NT = (BM/TM) * (BN/TN);
    __shared__ float As[BK][BM];
    __shared__ float Bs[BK][BN];

    const int z  = blockIdx.z;
    const int zo = z / innerCnt, zi = z - zo * innerCnt;
    const float* A = Ag + (long)zo * sAo + (long)zi * sAi;
    const float* B = Bg + (long)zo * sBo + (long)zi * sBi;
    float*       C = Cg + (long)zo * sCo + (long)zi * sCi;

    const int tid  = threadIdx.x;
    const int m0   = blockIdx.y * BM;
    const int n0   = blockIdx.x * BN;
    const int tcol = tid % (BN/TN);
    const int trow = tid / (BN/TN);

    float acc[TM][TN];
    #pragma unroll
    for (int i = 0; i < TM; i++)
        #pragma unroll
        for (int j = 0; j < TN; j++) acc[i][j] = 0.f;

    for (int k0 = 0; k0 < K; k0 += BK) {
        if constexpr (TA) {
            constexpr int L = BK*BM/4/NT;
            #pragma unroll
            for (int l = 0; l < L; l++) {
                int idx = tid + l*NT;
                int kk = idx / (BM/4), mq = idx % (BM/4);
                *(float4*)&As[kk][mq*4] =
                    *(const float4*)(A + (long)(k0+kk)*lda + (m0 + mq*4));
            }
        } else {
            constexpr int L = BM*BK/4/NT;
            #pragma unroll
            for (int l = 0; l < L; l++) {
                int idx = tid + l*NT;
                int mm = idx / (BK/4), kq = idx % (BK/4);
                float4 v = *(const float4*)(A + (long)(m0+mm)*lda + (k0 + kq*4));
                As[kq*4+0][mm] = v.x; As[kq*4+1][mm] = v.y;
                As[kq*4+2][mm] = v.z; As[kq*4+3][mm] = v.w;
            }
        }
        if constexpr (!TB) {
            constexpr int L = BK*BN/4/NT;
            #pragma unroll
            for (int l = 0; l < L; l++) {
                int idx = tid + l*NT;
                int kk = idx / (BN/4), nq = idx % (BN/4);
                *(float4*)&Bs[kk][nq*4] =
                    *(const float4*)(B + (long)(k0+kk)*ldb + (n0 + nq*4));
            }
        } else {
            constexpr int L = BN*BK/4/NT;
            #pragma unroll
            for (int l = 0; l < L; l++) {
                int idx = tid + l*NT;
                int nn = idx / (BK/4), kq = idx % (BK/4);
                float4 v = *(const float4*)(B + (long)(n0+nn)*ldb + (k0 + kq*4));
                Bs[kq*4+0][nn] = v.x; Bs[kq*4+1][nn] = v.y;
                Bs[kq*4+2][nn] = v.z; Bs[kq*4+3][nn] = v.w;
            }
        }
        __syncthreads();

        #pragma unroll
        for (int kk = 0; kk < BK; kk++) {
            float a[TM], b[TN];
            #pragma unroll
            for (int i = 0; i < TM; i += 4)
                *(float4*)&a[i] = *(float4*)&As[kk][trow*TM + i];
            #pragma unroll
            for (int j = 0; j < TN; j += 4)
                *(float4*)&b[j] = *(float4*)&Bs[kk][tcol*TN + j];
            #pragma unroll
            for (int i = 0; i < TM; i++)
                #pragma unroll
                for (int j = 0; j < TN; j++)
                    acc[i][j] += a[i] * b[j];
        }
        __syncthreads();
    }

    #pragma unroll
    for (int i = 0; i < TM; i++) {
        int m = m0 + trow*TM + i;
        float bval = BIAS ? bias[m] : 0.f;
        #pragma unroll
        for (int j = 0; j < TN; j += 4) {
            float4 v;
            v.x = acc[i][j+0] + bval;
            v.y = acc[i][j+1] + bval;
            v.z = acc[i][j+2] + bval;
            v.w = acc[i][j+3] + bval;
            *(float4*)(C + (long)m*ldc + (n0 + tcol*TN + j)) = v;
        }
    }
}

// ---------------------------------------------------------------------------
// Fused l2-normalize over head-dim + per-dim scales, in place on q,k regions.
// ---------------------------------------------------------------------------
__global__ void norm_scale_k(float* __restrict__ qkv,
                             const float* __restrict__ q_scale,
                             const float* __restrict__ k_scale)
{
    int gid = blockIdx.x * blockDim.x + threadIdx.x;
    int n   = gid & (Nn - 1);
    int h   = (gid >> 11) & (HEADS - 1);
    int sel = (gid >> 15) & 1;
    int b   = gid >> 16;

    float* p = qkv + ((long)b * 3 * HDIM + sel * HDIM + h * DHEAD) * Nn + n;
    float v[DHEAD];
    float ss = 0.f;
    #pragma unroll
    for (int d = 0; d < DHEAD; d++) {
        v[d] = p[(long)d * Nn];
        ss += v[d] * v[d];
    }
    float nrm = fmaxf(sqrtf(ss), 1e-12f);
    float inv = (sel ? 1.0f : 8.0f) / nrm;
    const float* sc = sel ? k_scale : q_scale;
    #pragma unroll
    for (int d = 0; d < DHEAD; d++)
        p[(long)d * Nn] = v[d] * inv * sc[d];
}

// ---------------------------------------------------------------------------
// Flash attention, tf32 WMMA m16n16k8.
// Grid: (N/128, B*HEADS). 256 threads = 8 warps. Each CTA: 128 q-rows, D=64.
// No max-shift: |S| <= 8 guaranteed (l2-normalized q,k; ||q||=8, ||k||=1).
// SMEM: Qs[64][LD] Ks[64][LD] Vs[64][LD] (tf32-rounded), Ss[128][LD], rowsum[128]
// ---------------------------------------------------------------------------
constexpr int LD = 132;  // 128 + 4 pad; multiple of 4 floats for wmma ldm
constexpr int FLASH_SMEM = (3*64*LD + 128*LD + 128) * 4;  // ~166 KB

__global__ void __launch_bounds__(256)
flash_k(const float* __restrict__ qkv, float* __restrict__ ao)
{
    extern __shared__ float sm[];
    float* Qs = sm;                  // 64 x LD  (d, i)
    float* Ks = Qs + 64*LD;          // 64 x LD  (d, j)
    float* Vs = Ks + 64*LD;          // 64 x LD  (d, j)
    float* Ss = Vs + 64*LD;          // 128 x LD (i, j)  / later O (i, d)
    float* rowsum = Ss + 128*LD;     // 128

    const int tid = threadIdx.x;
    const int wid = tid >> 5;
    const int qi0 = blockIdx.x * 128;
    const int bh  = blockIdx.y;
    const int b = bh >> 4, h = bh & 15;

    const float* qg = qkv + ((long)b*3*HDIM + h*DHEAD)*Nn;
    const float* kg = qg + (long)HDIM*Nn;
    const float* vg = qg + (long)2*HDIM*Nn;

    // Q tile -> smem, tf32-rounded
    for (int l = tid; l < 64*32; l += 256) {
        int d  = l >> 5;
        int iq = (l & 31) * 4;
        float4 v = *(const float4*)(qg + (long)d*Nn + qi0 + iq);
        float* dst = Qs + d*LD + iq;
        dst[0] = wmma::__float_to_tf32(v.x);
        dst[1] = wmma::__float_to_tf32(v.y);
        dst[2] = wmma::__float_to_tf32(v.z);
        dst[3] = wmma::__float_to_tf32(v.w);
    }
    if (tid < 128) rowsum[tid] = 0.f;

    wmma::fragment<wmma::accumulator,16,16,8,float> ofrag[4];
    #pragma unroll
    for (int c = 0; c < 4; c++) wmma::fill_fragment(ofrag[c], 0.f);

    const int r0 = wid * 16;   // this warp's 16 q-rows

    for (int kt = 0; kt < Nn; kt += 128) {
        __syncthreads();  // prev iter fully consumed Ks/Vs/Ss
        // K,V tiles -> smem, tf32-rounded
        for (int l = tid; l < 64*32; l += 256) {
            int d = l >> 5;
            int j = (l & 31) * 4;
            float4 v = *(const float4*)(kg + (long)d*Nn + kt + j);
            float* dk = Ks + d*LD + j;
            dk[0] = wmma::__float_to_tf32(v.x);
            dk[1] = wmma::__float_to_tf32(v.y);
            dk[2] = wmma::__float_to_tf32(v.z);
            dk[3] = wmma::__float_to_tf32(v.w);
            float4 w = *(const float4*)(vg + (long)d*Nn + kt + j);
            float* dv = Vs + d*LD + j;
            dv[0] = wmma::__float_to_tf32(w.x);
            dv[1] = wmma::__float_to_tf32(w.y);
            dv[2] = wmma::__float_to_tf32(w.z);
            dv[3] = wmma::__float_to_tf32(w.w);
        }
        __syncthreads();

        // S(i,j) = sum_d Q(d,i) K(d,j):  A col-major (i,d), B row-major (d,j)
        wmma::fragment<wmma::accumulator,16,16,8,float> sfrag[8];
        #pragma unroll
        for (int c = 0; c < 8; c++) wmma::fill_fragment(sfrag[c], 0.f);
        #pragma unroll
        for (int d0 = 0; d0 < 64; d0 += 8) {
            wmma::fragment<wmma::matrix_a,16,16,8,wmma::precision::tf32,wmma::col_major> af;
            wmma::load_matrix_sync(af, Qs + d0*LD + r0, LD);
            #pragma unroll
            for (int c = 0; c < 8; c++) {
                wmma::fragment<wmma::matrix_b,16,16,8,wmma::precision::tf32,wmma::row_major> bf;
                wmma::load_matrix_sync(bf, Ks + d0*LD + c*16, LD);
                wmma::mma_sync(sfrag[c], af, bf, sfrag[c]);
            }
        }
        #pragma unroll
        for (int c = 0; c < 8; c++)
            wmma::store_matrix_sync(Ss + r0*LD + c*16, sfrag[c], LD, wmma::mem_row_major);
        __syncthreads();

        // P = exp(S) (no shift), accumulate row sums, tf32-round P
        {
            int r  = tid >> 1;
            int c0 = (tid & 1) * 64;
            float* p = Ss + r*LD + c0;
            float s = 0.f;
            #pragma unroll
            for (int c = 0; c < 64; c++) {
                float e = __expf(p[c]);
                s += e;
                p[c] = wmma::__float_to_tf32(e);
            }
            s += __shfl_xor_sync(0xffffffffu, s, 1);
            if ((tid & 1) == 0) rowsum[r] += s;
        }
        __syncthreads();

        // O(i,d) += sum_j P(i,j) V(d,j): A row-major (i,j), B col-major (j,d)
        #pragma unroll
        for (int j0 = 0; j0 < 128; j0 += 8) {
            wmma::fragment<wmma::matrix_a,16,16,8,wmma::precision::tf32,wmma::row_major> af;
            wmma::load_matrix_sync(af, Ss + r0*LD + j0, LD);
            #pragma unroll
            for (int c = 0; c < 4; c++) {
                wmma::fragment<wmma::matrix_b,16,16,8,wmma::precision::tf32,wmma::col_major> bf;
                wmma::load_matrix_sync(bf, Vs + c*16*LD + j0, LD);
                wmma::mma_sync(ofrag[c], af, bf, ofrag[c]);
            }
        }
    }

    __syncthreads();
    // O frags -> Ss as (i, d), then normalize and write ao[d][i] (channel-major)
    #pragma unroll
    for (int c = 0; c < 4; c++)
        wmma::store_matrix_sync(Ss + r0*LD + c*16, ofrag[c], LD, wmma::mem_row_major);
    __syncthreads();

    float* aog = ao + ((long)b*HDIM + h*DHEAD)*Nn;
    for (int l = tid; l < 64*128; l += 256) {
        int d = l >> 7;
        int i = l & 127;
        aog[(long)d*Nn + qi0 + i] = Ss[i*LD + d] / rowsum[i];
    }
}

// ---------------------------------------------------------------------------
extern "C" void kernel_launch(void* const* d_in, const int* in_sizes, int n_in,
                              void* d_out, int out_size)
{
    (void)in_sizes; (void)n_in; (void)out_size;
    const float* x       = (const float*)d_in[0];
    const float* Wqkv    = (const float*)d_in[1];
    const float* q_scale = (const float*)d_in[2];
    const float* k_scale = (const float*)d_in[3];
    const float* Wout    = (const float*)d_in[4];
    const float* bout    = (const float*)d_in[5];
    float* out = (float*)d_out;

    float *qkv, *ao;
    cudaGetSymbolAddress((void**)&qkv, g_qkv);
    cudaGetSymbolAddress((void**)&ao,  g_ao);

    // 1) qkv = Wqkv @ x
    gemm_k<128,128,8,8,8,false,false,false>
        <<<dim3(Nn/128, 3072/128, Bb), 256>>>(
            Wqkv, x, qkv, nullptr,
            Cc, Cc, Nn, Nn,
            0, 0, (long)Cc*Nn, 0, (long)3*HDIM*Nn, 0, 1);

    // 2) l2-normalize q,k (+scales, SCALE folded into q), in place
    norm_scale_k<<<(Bb*2*HEADS*Nn)/256, 256>>>(qkv, q_scale, k_scale);

    // 3) fused flash attention -> ao (channel-major)
    static bool attr_set = false;
    if (!attr_set) {
        cudaFuncSetAttribute(flash_k, cudaFuncAttributeMaxDynamicSharedMemorySize,
                             FLASH_SMEM);
        attr_set = true;
    }
    flash_k<<<dim3(Nn/128, Bb*HEADS), 256, FLASH_SMEM>>>(qkv, ao);

    // 4) out = Wout @ AO + bout
    gemm_k<128,128,8,8,8,false,false,true>
        <<<dim3(Nn/128, Cc/128, Bb), 256>>>(
            Wout, ao, out, bout,
            HDIM, HDIM, Nn, Nn,
            0, 0, (long)HDIM*Nn, 0, (long)Cc*Nn, 0, 1);
}

// round 3
// speedup vs baseline: 1.6578x; 1.2674x over previous
#include <cuda_runtime.h>
#include <mma.h>

using namespace nvcuda;

// ---------------------------------------------------------------------------
// Attention_50921132261730 — R3: all-tensor tf32 pipeline
//   qkv = Wqkv @ x                 (tf32 WMMA gemm)
//   q,k <- l2norm * scales (SCALE folded into q)
//   flash: 2 CTA/SM, Q-in-regs, warp-private softmax (no max-shift, |S|<=8)
//   out = Wout @ AO (tf32 WMMA) then += bout
// ---------------------------------------------------------------------------

constexpr int Bb = 2, Cc = 512, Nn = 2048, HEADS = 16, DHEAD = 64;
constexpr int HDIM = HEADS * DHEAD;    // 1024

__device__ float g_qkv[(long)Bb * 3 * HDIM * Nn];
__device__ float g_ao [(long)Bb * HDIM * Nn];

__device__ __forceinline__ float t32(float x) { return wmma::__float_to_tf32(x); }

// ---------------------------------------------------------------------------
// tf32 WMMA GEMM:  C[z] = A @ B[z]
//   A [M,K] row-major (weights, shared across batch), lda = K
//   B [K,Nn] row-major per batch z, C [M,Nn] per batch z
// ---------------------------------------------------------------------------
template<int BM,int BN,int WM,int WN>
__global__ void __launch_bounds__(256)
wgemm_k(const float* __restrict__ Ag, const float* __restrict__ Bg,
        float* __restrict__ Cg, int K, long sB, long sC)
{
    constexpr int BK = 32, LDA = BM + 4, LDB = BN + 4;
    constexpr int NWN = BN / WN;
    __shared__ float As[BK * LDA];
    __shared__ float Bs[BK * LDB];

    const float* B = Bg + (long)blockIdx.z * sB;
    float*       C = Cg + (long)blockIdx.z * sC;
    const int tid = threadIdx.x, wid = tid >> 5;
    const int m0 = blockIdx.y * BM, n0 = blockIdx.x * BN;
    const int wm = (wid / NWN) * WM, wn = (wid % NWN) * WN;

    wmma::fragment<wmma::accumulator,16,16,8,float> acc[WM/16][WN/16];
    #pragma unroll
    for (int i = 0; i < WM/16; i++)
        #pragma unroll
        for (int j = 0; j < WN/16; j++) wmma::fill_fragment(acc[i][j], 0.f);

    for (int k0 = 0; k0 < K; k0 += BK) {
        // A tile [BM x BK] -> As[k][m] (transposed, tf32-rounded)
        #pragma unroll
        for (int l = tid; l < BM*(BK/4); l += 256) {
            int mm = l / (BK/4), kq = l % (BK/4);
            float4 v = *(const float4*)(Ag + (long)(m0+mm)*K + k0 + kq*4);
            As[(kq*4+0)*LDA + mm] = t32(v.x);
            As[(kq*4+1)*LDA + mm] = t32(v.y);
            As[(kq*4+2)*LDA + mm] = t32(v.z);
            As[(kq*4+3)*LDA + mm] = t32(v.w);
        }
        // B tile [BK x BN] -> Bs[k][n]
        #pragma unroll
        for (int l = tid; l < BK*(BN/4); l += 256) {
            int kk = l / (BN/4), nq = l % (BN/4);
            float4 v = *(const float4*)(B + (long)(k0+kk)*Nn + n0 + nq*4);
            float* d = &Bs[kk*LDB + nq*4];
            d[0] = t32(v.x); d[1] = t32(v.y); d[2] = t32(v.z); d[3] = t32(v.w);
        }
        __syncthreads();

        #pragma unroll
        for (int kc = 0; kc < BK; kc += 8) {
            wmma::fragment<wmma::matrix_a,16,16,8,wmma::precision::tf32,wmma::col_major> af[WM/16];
            #pragma unroll
            for (int i = 0; i < WM/16; i++)
                wmma::load_matrix_sync(af[i], As + kc*LDA + wm + i*16, LDA);
            #pragma unroll
            for (int j = 0; j < WN/16; j++) {
                wmma::fragment<wmma::matrix_b,16,16,8,wmma::precision::tf32,wmma::row_major> bf;
                wmma::load_matrix_sync(bf, Bs + kc*LDB + wn + j*16, LDB);
                #pragma unroll
                for (int i = 0; i < WM/16; i++)
                    wmma::mma_sync(acc[i][j], af[i], bf, acc[i][j]);
            }
        }
        __syncthreads();
    }

    #pragma unroll
    for (int i = 0; i < WM/16; i++)
        #pragma unroll
        for (int j = 0; j < WN/16; j++)
            wmma::store_matrix_sync(C + (long)(m0+wm+i*16)*Nn + n0 + wn + j*16,
                                    acc[i][j], Nn, wmma::mem_row_major);
}

// ---------------------------------------------------------------------------
// Fused l2-normalize over head-dim + per-dim scales, in place on q,k regions.
// ---------------------------------------------------------------------------
__global__ void norm_scale_k(float* __restrict__ qkv,
                             const float* __restrict__ q_scale,
                             const float* __restrict__ k_scale)
{
    int gid = blockIdx.x * blockDim.x + threadIdx.x;
    int n   = gid & (Nn - 1);
    int h   = (gid >> 11) & (HEADS - 1);
    int sel = (gid >> 15) & 1;
    int b   = gid >> 16;

    float* p = qkv + ((long)b * 3 * HDIM + sel * HDIM + h * DHEAD) * Nn + n;
    float v[DHEAD];
    float ss = 0.f;
    #pragma unroll
    for (int d = 0; d < DHEAD; d++) {
        v[d] = p[(long)d * Nn];
        ss += v[d] * v[d];
    }
    float nrm = fmaxf(sqrtf(ss), 1e-12f);
    float inv = (sel ? 1.0f : 8.0f) / nrm;
    const float* sc = sel ? k_scale : q_scale;
    #pragma unroll
    for (int d = 0; d < DHEAD; d++)
        p[(long)d * Nn] = v[d] * inv * sc[d];
}

// ---------------------------------------------------------------------------
// Flash attention: Q-tile 64 rows, 4 warps (16 rows each), Q frags in regs.
// smem = Ks + Vs + Ss = ~102KB -> 2 CTAs/SM. Warp-private S rows: the
// S-store -> exp -> PV chain needs only __syncwarp.
// ---------------------------------------------------------------------------
constexpr int FLD = 132;   // 128 + 4 pad
constexpr int LDQ = 68;    // 64 + 4 pad (Q staging / O epilogue in Ss)
constexpr int FLASH_SMEM = (3*64*FLD + 64) * 4;   // 101,632 B

__global__ void __launch_bounds__(128, 2)
flash_k(const float* __restrict__ qkv, float* __restrict__ ao)
{
    extern __shared__ float sm[];
    float* Ks = sm;                 // (d, j)  64 x FLD
    float* Vs = sm + 64*FLD;        // (d, j)  64 x FLD
    float* Ss = sm + 2*64*FLD;      // (i, j)  64 x FLD  (also Q stage / O out)
    float* rowsum = sm + 3*64*FLD;  // 64

    const int tid = threadIdx.x, wid = tid >> 5, lane = tid & 31;
    const int qi0 = blockIdx.x * 64;
    const int bh = blockIdx.y;
    const int b = bh >> 4, h = bh & 15;

    const float* qg = qkv + ((long)b*3*HDIM + h*DHEAD)*Nn;
    const float* kg = qg + (long)HDIM*Nn;
    const float* vg = qg + (long)2*HDIM*Nn;

    // ---- Q stage: (d,i) 64x64 into Ss (tf32-rounded) ----
    for (int l = tid; l < 64*16; l += 128) {
        int d = l >> 4, i4 = (l & 15) * 4;
        float4 v = *(const float4*)(qg + (long)d*Nn + qi0 + i4);
        float* dst = Ss + d*LDQ + i4;
        dst[0] = t32(v.x); dst[1] = t32(v.y); dst[2] = t32(v.z); dst[3] = t32(v.w);
    }
    if (tid < 64) rowsum[tid] = 0.f;
    __syncthreads();

    const int r0 = wid * 16;
    wmma::fragment<wmma::matrix_a,16,16,8,wmma::precision::tf32,wmma::col_major> qf[8];
    #pragma unroll
    for (int dc = 0; dc < 8; dc++)
        wmma::load_matrix_sync(qf[dc], Ss + dc*8*LDQ + r0, LDQ);

    wmma::fragment<wmma::accumulator,16,16,8,float> of[4];
    #pragma unroll
    for (int c = 0; c < 4; c++) wmma::fill_fragment(of[c], 0.f);

    for (int kt = 0; kt < Nn; kt += 128) {
        __syncthreads();   // all warps done with prev Ks/Vs/Ss (and Q stage)
        // ---- K,V tiles -> smem (tf32-rounded) ----
        for (int l = tid; l < 64*32; l += 128) {
            int d = l >> 5, j4 = (l & 31) * 4;
            float4 v = *(const float4*)(kg + (long)d*Nn + kt + j4);
            float* dk = Ks + d*FLD + j4;
            dk[0] = t32(v.x); dk[1] = t32(v.y); dk[2] = t32(v.z); dk[3] = t32(v.w);
            float4 w = *(const float4*)(vg + (long)d*Nn + kt + j4);
            float* dv = Vs + d*FLD + j4;
            dv[0] = t32(w.x); dv[1] = t32(w.y); dv[2] = t32(w.z); dv[3] = t32(w.w);
        }
        __syncthreads();

        // ---- S = Q^T K : warp computes 16 rows x 128 cols ----
        wmma::fragment<wmma::accumulator,16,16,8,float> sf[8];
        #pragma unroll
        for (int j = 0; j < 8; j++) wmma::fill_fragment(sf[j], 0.f);
        #pragma unroll
        for (int dc = 0; dc < 8; dc++) {
            #pragma unroll
            for (int j = 0; j < 8; j++) {
                wmma::fragment<wmma::matrix_b,16,16,8,wmma::precision::tf32,wmma::row_major> bf;
                wmma::load_matrix_sync(bf, Ks + dc*8*FLD + j*16, FLD);
                wmma::mma_sync(sf[j], qf[dc], bf, sf[j]);
            }
        }
        #pragma unroll
        for (int j = 0; j < 8; j++)
            wmma::store_matrix_sync(Ss + r0*FLD + j*16, sf[j], FLD, wmma::mem_row_major);
        __syncwarp();

        // ---- P = exp(S), rowsum (warp-private rows) ----
        {
            int r = r0 + (lane >> 1);
            float4* p = (float4*)(Ss + r*FLD + (lane & 1) * 64);
            float s = 0.f;
            #pragma unroll
            for (int c = 0; c < 16; c++) {
                float4 v = p[c];
                v.x = __expf(v.x); v.y = __expf(v.y);
                v.z = __expf(v.z); v.w = __expf(v.w);
                s += v.x + v.y + v.z + v.w;
                v.x = t32(v.x); v.y = t32(v.y); v.z = t32(v.z); v.w = t32(v.w);
                p[c] = v;
            }
            s += __shfl_xor_sync(0xffffffffu, s, 1);
            if (!(lane & 1)) rowsum[r] += s;
        }
        __syncwarp();

        // ---- O += P @ V^T : warp 16 rows x 64 d ----
        #pragma unroll
        for (int j0 = 0; j0 < 128; j0 += 8) {
            wmma::fragment<wmma::matrix_a,16,16,8,wmma::precision::tf32,wmma::row_major> af;
            wmma::load_matrix_sync(af, Ss + r0*FLD + j0, FLD);
            #pragma unroll
            for (int c = 0; c < 4; c++) {
                wmma::fragment<wmma::matrix_b,16,16,8,wmma::precision::tf32,wmma::col_major> bf;
                wmma::load_matrix_sync(bf, Vs + c*16*FLD + j0, FLD);
                wmma::mma_sync(of[c], af, bf, of[c]);
            }
        }
    }

    __syncthreads();
    // ---- O frags -> Ss as (i, d), normalize, write ao (channel-major) ----
    #pragma unroll
    for (int c = 0; c < 4; c++)
        wmma::store_matrix_sync(Ss + r0*LDQ + c*16, of[c], LDQ, wmma::mem_row_major);
    __syncthreads();

    float* aog = ao + ((long)b*HDIM + h*DHEAD)*Nn;
    for (int l = tid; l < 64*64; l += 128) {
        int i = l & 63, d = l >> 6;
        aog[(long)d*Nn + qi0 + i] = Ss[i*LDQ + d] / rowsum[i];
    }
}

// ---------------------------------------------------------------------------
// out[b][c][n] += bout[c]
// ---------------------------------------------------------------------------
__global__ void bias_k(float* __restrict__ out, const float* __restrict__ bout)
{
    long i = (long)blockIdx.x * 256 + threadIdx.x;   // float4 index
    int c = (int)((i >> 9) & 511);
    float bv = bout[c];
    float4* p = (float4*)out;
    float4 v = p[i];
    v.x += bv; v.y += bv; v.z += bv; v.w += bv;
    p[i] = v;
}

// ---------------------------------------------------------------------------
extern "C" void kernel_launch(void* const* d_in, const int* in_sizes, int n_in,
                              void* d_out, int out_size)
{
    (void)in_sizes; (void)n_in; (void)out_size;
    const float* x       = (const float*)d_in[0];
    const float* Wqkv    = (const float*)d_in[1];
    const float* q_scale = (const float*)d_in[2];
    const float* k_scale = (const float*)d_in[3];
    const float* Wout    = (const float*)d_in[4];
    const float* bout    = (const float*)d_in[5];
    float* out = (float*)d_out;

    float *qkv, *ao;
    cudaGetSymbolAddress((void**)&qkv, g_qkv);
    cudaGetSymbolAddress((void**)&ao,  g_ao);

    cudaFuncSetAttribute(flash_k, cudaFuncAttributeMaxDynamicSharedMemorySize,
                         FLASH_SMEM);

    // 1) qkv = Wqkv @ x   (M=3072, K=512)
    wgemm_k<128,128,64,32><<<dim3(Nn/128, 3072/128, Bb), 256>>>(
        Wqkv, x, qkv, Cc, (long)Cc*Nn, (long)3*HDIM*Nn);

    // 2) l2-normalize q,k (+scales, SCALE folded into q)
    norm_scale_k<<<(Bb*2*HEADS*Nn)/256, 256>>>(qkv, q_scale, k_scale);

    // 3) fused flash attention -> ao (channel-major)
    flash_k<<<dim3(Nn/64, Bb*HEADS), 128, FLASH_SMEM>>>(qkv, ao);

    // 4) out = Wout @ ao   (M=512, K=1024)
    wgemm_k<64,128,32,32><<<dim3(Nn/128, Cc/64, Bb), 256>>>(
        Wout, ao, out, HDIM, (long)HDIM*Nn, (long)Cc*Nn);

    // 5) out += bout
    bias_k<<<(Bb*Cc*Nn/4)/256, 256>>>(out, bout);
}

// round 5
// speedup vs baseline: 1.9644x; 1.1849x over previous
#include <cuda_runtime.h>
#include <mma.h>

using namespace nvcuda;

// ---------------------------------------------------------------------------
// Attention_50921132261730 — R5: legacy-path optimized (compute_103-safe)
//   qkv = Wqkv @ x            (tf32 WMMA, double-buffered)
//   q,k <- l2norm * scales (SCALE folded into q), in place
//   flash: tf32 WMMA, 2x2 warp split, warp-private S/exp/PV chain,
//          per-thread rowsum, one cross-warp reduce at end
//   out = Wout @ ao (tf32 WMMA, double-buffered) + bout
// ---------------------------------------------------------------------------

constexpr int Bb = 2, Cc = 512, Nn = 2048, HEADS = 16, DHEAD = 64;
constexpr int HDIM = HEADS * DHEAD;    // 1024

__device__ float g_qkv[(long)Bb * 3 * HDIM * Nn];
__device__ float g_ao [(long)Bb * HDIM * Nn];

__device__ __forceinline__ float t32(float x) { return wmma::__float_to_tf32(x); }

// ---------------------------------------------------------------------------
// Double-buffered tf32 WMMA GEMM: C[z] = A @ B[z]
//   A [M,K] row-major (weights, no batch), B [K,Nn] row-major per batch z.
//   128 threads, BK=16, 2-stage smem, register-staged global loads.
// ---------------------------------------------------------------------------
template<int BM,int BN,int WM,int WN>
__global__ void __launch_bounds__(128)
wgemm2(const float* __restrict__ Ag, const float* __restrict__ Bg,
       float* __restrict__ Cg, int K, long sB, long sC)
{
    constexpr int NT = 128, BK = 16, LDA = BM + 4, LDB = BN + 4;
    constexpr int NWN = BN / WN;
    constexpr int AF4 = BM * BK / (4 * NT);
    constexpr int BF4 = BK * BN / (4 * NT);
    __shared__ float As[2][BK * LDA];
    __shared__ float Bs[2][BK * LDB];

    const float* B = Bg + (long)blockIdx.z * sB;
    float*       C = Cg + (long)blockIdx.z * sC;
    const int tid = threadIdx.x, wid = tid >> 5;
    const int m0 = blockIdx.y * BM, n0 = blockIdx.x * BN;
    const int wm = (wid / NWN) * WM, wn = (wid % NWN) * WN;

    wmma::fragment<wmma::accumulator,16,16,8,float> acc[WM/16][WN/16];
    #pragma unroll
    for (int i = 0; i < WM/16; i++)
        #pragma unroll
        for (int j = 0; j < WN/16; j++) wmma::fill_fragment(acc[i][j], 0.f);

    float4 ra[AF4], rb[BF4];

    auto ldg = [&](int k0) {
        #pragma unroll
        for (int a = 0; a < AF4; a++) {
            int idx = tid + a*NT, mm = idx / (BK/4), kq = idx % (BK/4);
            ra[a] = *(const float4*)(Ag + (long)(m0+mm)*K + k0 + kq*4);
        }
        #pragma unroll
        for (int bi = 0; bi < BF4; bi++) {
            int idx = tid + bi*NT, kk = idx / (BN/4), nq = idx % (BN/4);
            rb[bi] = *(const float4*)(B + (long)(k0+kk)*Nn + n0 + nq*4);
        }
    };
    auto sts = [&](int buf) {
        #pragma unroll
        for (int a = 0; a < AF4; a++) {
            int idx = tid + a*NT, mm = idx / (BK/4), kq = idx % (BK/4);
            As[buf][(kq*4+0)*LDA + mm] = t32(ra[a].x);
            As[buf][(kq*4+1)*LDA + mm] = t32(ra[a].y);
            As[buf][(kq*4+2)*LDA + mm] = t32(ra[a].z);
            As[buf][(kq*4+3)*LDA + mm] = t32(ra[a].w);
        }
        #pragma unroll
        for (int bi = 0; bi < BF4; bi++) {
            int idx = tid + bi*NT, kk = idx / (BN/4), nq = idx % (BN/4);
            *(float4*)&Bs[buf][kk*LDB + nq*4] =
                make_float4(t32(rb[bi].x), t32(rb[bi].y), t32(rb[bi].z), t32(rb[bi].w));
        }
    };

    const int nI = K / BK;
    ldg(0);
    sts(0);
    __syncthreads();

    for (int it = 0; it < nI; it++) {
        const int cur = it & 1;
        if (it + 1 < nI) ldg((it + 1) * BK);

        #pragma unroll
        for (int kc = 0; kc < BK; kc += 8) {
            wmma::fragment<wmma::matrix_a,16,16,8,wmma::precision::tf32,wmma::col_major> af[WM/16];
            #pragma unroll
            for (int i = 0; i < WM/16; i++)
                wmma::load_matrix_sync(af[i], &As[cur][kc*LDA + wm + i*16], LDA);
            #pragma unroll
            for (int j = 0; j < WN/16; j++) {
                wmma::fragment<wmma::matrix_b,16,16,8,wmma::precision::tf32,wmma::row_major> bf;
                wmma::load_matrix_sync(bf, &Bs[cur][kc*LDB + wn + j*16], LDB);
                #pragma unroll
                for (int i = 0; i < WM/16; i++)
                    wmma::mma_sync(acc[i][j], af[i], bf, acc[i][j]);
            }
        }

        if (it + 1 < nI) sts(cur ^ 1);
        __syncthreads();
    }

    #pragma unroll
    for (int i = 0; i < WM/16; i++)
        #pragma unroll
        for (int j = 0; j < WN/16; j++)
            wmma::store_matrix_sync(C + (long)(m0+wm+i*16)*Nn + n0 + wn + j*16,
                                    acc[i][j], Nn, wmma::mem_row_major);
}

// ---------------------------------------------------------------------------
// Fused l2-normalize over head-dim + per-dim scales, in place on q,k regions.
// ---------------------------------------------------------------------------
__global__ void norm_scale_k(float* __restrict__ qkv,
                             const float* __restrict__ q_scale,
                             const float* __restrict__ k_scale)
{
    int gid = blockIdx.x * blockDim.x + threadIdx.x;
    int n   = gid & (Nn - 1);
    int h   = (gid >> 11) & (HEADS - 1);
    int sel = (gid >> 15) & 1;
    int b   = gid >> 16;

    float* p = qkv + ((long)b * 3 * HDIM + sel * HDIM + h * DHEAD) * Nn + n;
    float v[DHEAD];
    float ss = 0.f;
    #pragma unroll
    for (int d = 0; d < DHEAD; d++) {
        v[d] = p[(long)d * Nn];
        ss += v[d] * v[d];
    }
    float nrm = fmaxf(sqrtf(ss), 1e-12f);
    float inv = (sel ? 1.0f : 8.0f) / nrm;
    const float* sc = sel ? k_scale : q_scale;
    #pragma unroll
    for (int d = 0; d < DHEAD; d++)
        p[(long)d * Nn] = v[d] * inv * sc[d];
}

// ---------------------------------------------------------------------------
// Flash attention, tf32 WMMA, 2x2 warp split.
// CTA: 64 q-rows, 128 threads (4 warps). Warp (r,c): S block rows r*32..+32,
// cols c*64..+64 of the 128-wide KV tile. Q frags in regs; S/exp/PV chain is
// warp-private (only K/V fills need CTA barriers). Rowsum per-thread over the
// warp's col-slice; partial O + rowsum reduced across the warp pair once.
// smem: Ks[64][FLD] Vs[64][FLD] (128-col KV tile, d-major) + 4x Sw[32][68] + rs
// ---------------------------------------------------------------------------
constexpr int FLD  = 132;   // 128 + 4
constexpr int SLD  = 68;    // 64 + 4
constexpr int KS_OFF = 0;
constexpr int VS_OFF = 64*FLD;                 // 8448
constexpr int SS_OFF = 2*64*FLD;               // 16896
constexpr int RS_OFF = SS_OFF + 4*32*SLD;      // 25600
constexpr int FLASH_SMEM = (RS_OFF + 128) * 4; // 102,912 B

__global__ void __launch_bounds__(128, 2)
flash2(const float* __restrict__ qkv, float* __restrict__ ao)
{
    extern __shared__ float sm[];
    float* Ks  = sm + KS_OFF;
    float* Vs  = sm + VS_OFF;
    float* Ssb = sm + SS_OFF;
    float* rs  = sm + RS_OFF;

    const int tid = threadIdx.x, wid = tid >> 5, lane = tid & 31;
    const int r = wid >> 1, c = wid & 1;
    const int qi0 = blockIdx.x * 64;
    const int bh = blockIdx.y;
    const int b = bh >> 4, h = bh & 15;

    const float* qg = qkv + ((long)b*3*HDIM + h*DHEAD)*Nn;
    const float* kg = qg + (long)HDIM*Nn;
    const float* vg = qg + (long)2*HDIM*Nn;

    // ---- Q stage (d,i) 64x64 into Ssb (tf32) ----
    for (int l = tid; l < 64*16; l += 128) {
        int d = l >> 4, i4 = (l & 15) * 4;
        float4 v = *(const float4*)(qg + (long)d*Nn + qi0 + i4);
        *(float4*)(Ssb + d*SLD + i4) =
            make_float4(t32(v.x), t32(v.y), t32(v.z), t32(v.w));
    }
    __syncthreads();

    // ---- Q frags: warp's 32 rows (2 m-blocks) x 8 d-chunks ----
    wmma::fragment<wmma::matrix_a,16,16,8,wmma::precision::tf32,wmma::col_major> qf[2][8];
    #pragma unroll
    for (int m = 0; m < 2; m++)
        #pragma unroll
        for (int dc = 0; dc < 8; dc++)
            wmma::load_matrix_sync(qf[m][dc], Ssb + dc*8*SLD + r*32 + m*16, SLD);

    wmma::fragment<wmma::accumulator,16,16,8,float> of[2][4];
    #pragma unroll
    for (int m = 0; m < 2; m++)
        #pragma unroll
        for (int dt = 0; dt < 4; dt++) wmma::fill_fragment(of[m][dt], 0.f);

    float rowsum = 0.f;
    float* Sw = Ssb + wid * (32*SLD);
    __syncthreads();   // qf loads done before Ssb reused as S

    for (int kt = 0; kt < Nn; kt += 128) {
        // ---- fill K,V tiles (shared, tf32) ----
        for (int l = tid; l < 64*32; l += 128) {
            int d = l >> 5, j4 = (l & 31) * 4;
            float4 v = *(const float4*)(kg + (long)d*Nn + kt + j4);
            *(float4*)(Ks + d*FLD + j4) =
                make_float4(t32(v.x), t32(v.y), t32(v.z), t32(v.w));
            float4 w = *(const float4*)(vg + (long)d*Nn + kt + j4);
            *(float4*)(Vs + d*FLD + j4) =
                make_float4(t32(w.x), t32(w.y), t32(w.z), t32(w.w));
        }
        __syncthreads();

        // ---- S = Q^T K : 32 rows x 64-col slice ----
        wmma::fragment<wmma::accumulator,16,16,8,float> sf[2][4];
        #pragma unroll
        for (int m = 0; m < 2; m++)
            #pragma unroll
            for (int j = 0; j < 4; j++) wmma::fill_fragment(sf[m][j], 0.f);
        #pragma unroll
        for (int dc = 0; dc < 8; dc++) {
            #pragma unroll
            for (int j = 0; j < 4; j++) {
                wmma::fragment<wmma::matrix_b,16,16,8,wmma::precision::tf32,wmma::row_major> bf;
                wmma::load_matrix_sync(bf, Ks + dc*8*FLD + c*64 + j*16, FLD);
                wmma::mma_sync(sf[0][j], qf[0][dc], bf, sf[0][j]);
                wmma::mma_sync(sf[1][j], qf[1][dc], bf, sf[1][j]);
            }
        }
        #pragma unroll
        for (int m = 0; m < 2; m++)
            #pragma unroll
            for (int j = 0; j < 4; j++)
                wmma::store_matrix_sync(Sw + m*16*SLD + j*16, sf[m][j], SLD,
                                        wmma::mem_row_major);
        __syncwarp();

        // ---- P = exp(S) (no max-shift, |S|<=8); per-thread rowsum ----
        {
            float4* p = (float4*)(Sw + lane*SLD);
            float s = 0.f;
            #pragma unroll
            for (int g = 0; g < 16; g++) {
                float4 v = p[g];
                v.x = __expf(v.x); v.y = __expf(v.y);
                v.z = __expf(v.z); v.w = __expf(v.w);
                s += v.x + v.y + v.z + v.w;
                p[g] = make_float4(t32(v.x), t32(v.y), t32(v.z), t32(v.w));
            }
            rowsum += s;
        }
        __syncwarp();

        // ---- O += P @ V^T over this warp's 64-j slice ----
        #pragma unroll
        for (int j0 = 0; j0 < 8; j0++) {
            wmma::fragment<wmma::matrix_a,16,16,8,wmma::precision::tf32,wmma::row_major> af[2];
            #pragma unroll
            for (int m = 0; m < 2; m++)
                wmma::load_matrix_sync(af[m], Sw + m*16*SLD + j0*8, SLD);
            #pragma unroll
            for (int dt = 0; dt < 4; dt++) {
                wmma::fragment<wmma::matrix_b,16,16,8,wmma::precision::tf32,wmma::col_major> bf;
                wmma::load_matrix_sync(bf, Vs + dt*16*FLD + c*64 + j0*8, FLD);
                wmma::mma_sync(of[0][dt], af[0], bf, of[0][dt]);
                wmma::mma_sync(of[1][dt], af[1], bf, of[1][dt]);
            }
        }
        __syncthreads();   // all warps done with Ks/Vs before next fill
    }

    // ---- reduce partial O + rowsum across the warp pair; write ao ----
    #pragma unroll
    for (int m = 0; m < 2; m++)
        #pragma unroll
        for (int dt = 0; dt < 4; dt++)
            wmma::store_matrix_sync(Sw + m*16*SLD + dt*16, of[m][dt], SLD,
                                    wmma::mem_row_major);
    rs[wid*32 + lane] = rowsum;
    __syncthreads();

    {
        const int i = tid & 63, db = (tid >> 6) * 32;
        const int wA = (i >> 5) * 2, il = i & 31;
        float inv = 1.0f / (rs[wA*32 + il] + rs[(wA+1)*32 + il]);
        const float* SA = Ssb + wA*(32*SLD) + il*SLD;
        const float* SB = SA + 32*SLD;
        float* aog = ao + ((long)b*HDIM + h*DHEAD)*Nn + qi0 + i;
        #pragma unroll
        for (int d = 0; d < 32; d++) {
            int dd = db + d;
            aog[(long)dd*Nn] = (SA[dd] + SB[dd]) * inv;
        }
    }
}

// ---------------------------------------------------------------------------
__global__ void bias_k(float* __restrict__ out, const float* __restrict__ bout)
{
    long i = (long)blockIdx.x * 256 + threadIdx.x;
    int c = (int)((i >> 9) & 511);
    float bv = bout[c];
    float4* p = (float4*)out;
    float4 v = p[i];
    v.x += bv; v.y += bv; v.z += bv; v.w += bv;
    p[i] = v;
}

// ---------------------------------------------------------------------------
extern "C" void kernel_launch(void* const* d_in, const int* in_sizes, int n_in,
                              void* d_out, int out_size)
{
    (void)in_sizes; (void)n_in; (void)out_size;
    const float* x       = (const float*)d_in[0];
    const float* Wqkv    = (const float*)d_in[1];
    const float* q_scale = (const float*)d_in[2];
    const float* k_scale = (const float*)d_in[3];
    const float* Wout    = (const float*)d_in[4];
    const float* bout    = (const float*)d_in[5];
    float* out = (float*)d_out;

    float *qkv, *ao;
    cudaGetSymbolAddress((void**)&qkv, g_qkv);
    cudaGetSymbolAddress((void**)&ao,  g_ao);

    cudaFuncSetAttribute(flash2, cudaFuncAttributeMaxDynamicSharedMemorySize,
                         FLASH_SMEM);

    // 1) qkv = Wqkv @ x   (M=3072, K=512)
    wgemm2<128,128,64,64><<<dim3(Nn/128, 3072/128, Bb), 128>>>(
        Wqkv, x, qkv, Cc, (long)Cc*Nn, (long)3*HDIM*Nn);

    // 2) l2-normalize q,k (+scales, SCALE folded into q)
    norm_scale_k<<<(Bb*2*HEADS*Nn)/256, 256>>>(qkv, q_scale, k_scale);

    // 3) flash attention -> ao (channel-major)
    flash2<<<dim3(Nn/64, Bb*HEADS), 128, FLASH_SMEM>>>(qkv, ao);

    // 4) out = Wout @ ao   (M=512, K=1024)
    wgemm2<64,128,32,64><<<dim3(Nn/128, Cc/64, Bb), 128>>>(
        Wout, ao, out, HDIM, (long)HDIM*Nn, (long)Cc*Nn);

    // 5) out += bout
    bias_k<<<(Bb*Cc*Nn/4)/256, 256>>>(out, bout);
}